// round 9
// baseline (speedup 1.0000x reference)
#include <cuda_runtime.h>

// ProbsToSpan: per batch b,
//   predicted_start[b] = argmax_s ( start[b,s] * suffix_max(end[b,:])[s] )
//   predicted_end[b]   = argmax_t ( end[b,t]   * prefix_max(start[b,:])[t] )
// Exact vs. reference (nonneg probs => monotone fp32 multiply; tie -> first idx).
//
// S=4096, B=16. One CTA/batch, 256 threads (8 warps), 16 elems/thread.
// Warp-shuffle scans; argmax via REDUX + ballot. 2 __syncthreads total.

#define S_LEN 4096
#define NT    256
#define NW    8     // warps
#define CHK   16    // elements per thread

#define NEGBIG (-1e30f)
#define FULLM  0xFFFFFFFFu

__global__ __launch_bounds__(NT)
void probs_to_span_kernel(const float* __restrict__ start_p,
                          const float* __restrict__ end_p,
                          float* __restrict__ out, int B) {
    __shared__ float wS[NW];               // per-warp total max(start)
    __shared__ float wE[NW];               // per-warp total max(end)
    __shared__ unsigned aVS[NW], aVE[NW];  // per-warp best value bits
    __shared__ int      aIS[NW], aIE[NW];  // per-warp best index

    const int b    = blockIdx.x;
    const int t    = threadIdx.x;
    const int w    = t >> 5;
    const int lane = t & 31;

    const float4* sp = (const float4*)(start_p + (size_t)b * S_LEN);
    const float4* ep = (const float4*)(end_p   + (size_t)b * S_LEN);

    // 4 float4 per array per thread: MLP=8, one DRAM round trip.
    float s[CHK], e[CHK];
#pragma unroll
    for (int q = 0; q < 4; q++) {
        float4 sv = sp[4 * t + q];
        float4 ev = ep[4 * t + q];
        s[4 * q + 0] = sv.x; s[4 * q + 1] = sv.y; s[4 * q + 2] = sv.z; s[4 * q + 3] = sv.w;
        e[4 * q + 0] = ev.x; e[4 * q + 1] = ev.y; e[4 * q + 2] = ev.z; e[4 * q + 3] = ev.w;
    }

    // Chunk maxes with 4-way ILP.
    float ps0 = s[0], ps1 = s[1], ps2 = s[2], ps3 = s[3];
    float pe0 = e[0], pe1 = e[1], pe2 = e[2], pe3 = e[3];
#pragma unroll
    for (int j = 4; j < CHK; j += 4) {
        ps0 = fmaxf(ps0, s[j]);     pe0 = fmaxf(pe0, e[j]);
        ps1 = fmaxf(ps1, s[j + 1]); pe1 = fmaxf(pe1, e[j + 1]);
        ps2 = fmaxf(ps2, s[j + 2]); pe2 = fmaxf(pe2, e[j + 2]);
        ps3 = fmaxf(ps3, s[j + 3]); pe3 = fmaxf(pe3, e[j + 3]);
    }
    float smax = fmaxf(fmaxf(ps0, ps1), fmaxf(ps2, ps3));
    float emax = fmaxf(fmaxf(pe0, pe1), fmaxf(pe2, pe3));

    // Warp-level inclusive prefix max of smax (by lane) and suffix max of emax.
    float ps = smax, se = emax;
#pragma unroll
    for (int off = 1; off < 32; off <<= 1) {
        float vU = __shfl_up_sync(FULLM, ps, off);
        float vD = __shfl_down_sync(FULLM, se, off);
        if (lane >= off)      ps = fmaxf(ps, vU);
        if (lane + off < 32)  se = fmaxf(se, vD);
    }

    // Publish warp totals.
    if (lane == 31) wS[w] = ps;   // inclusive prefix at lane31 == warp total
    if (lane == 0)  wE[w] = se;   // inclusive suffix at lane0  == warp total
    __syncthreads();

    // Cross-warp exclusive head(start) / tail(end) (uniform per warp, broadcast LDS).
    float headS = NEGBIG, tailE = NEGBIG;
#pragma unroll
    for (int i = 0; i < NW; i++) {
        if (i < w) headS = fmaxf(headS, wS[i]);
        if (i > w) tailE = fmaxf(tailE, wE[i]);
    }

    // Exclusive within-warp versions.
    float exS = __shfl_up_sync(FULLM, ps, 1);
    float exE = __shfl_down_sync(FULLM, se, 1);
    if (lane == 0)  exS = NEGBIG;
    if (lane == 31) exE = NEGBIG;

    const float preS = fmaxf(headS, exS);   // max(start) strictly before this chunk
    const float sufE = fmaxf(tailE, exE);   // max(end)   strictly after  this chunk

    // Best start: reverse loop computes suffix-max(end) on the fly.
    // Descending j with >= keeps the SMALLEST index on ties.
    float bvS = -1.0f; int biS = 0;
    float runE = sufE;
#pragma unroll
    for (int j = CHK - 1; j >= 0; j--) {
        runE = fmaxf(runE, e[j]);
        float f = s[j] * runE;
        if (f >= bvS) { bvS = f; biS = t * CHK + j; }
    }

    // Best end: forward loop with prefix-max(start); strict > keeps first index.
    float bvE = -1.0f; int biE = 0;
    float runS = preS;
#pragma unroll
    for (int j = 0; j < CHK; j++) {
        runS = fmaxf(runS, s[j]);
        float g = e[j] * runS;
        if (g > bvE) { bvE = g; biE = t * CHK + j; }
    }

    // Warp argmax via REDUX on fp32 bits (nonneg => order-monotone), then
    // ballot: lowest matching lane holds the smallest index.
    {
        unsigned vb = __float_as_uint(fmaxf(bvS, 0.0f));
        unsigned m  = __reduce_max_sync(FULLM, vb);
        unsigned msk = __ballot_sync(FULLM, vb == m);
        int src = __ffs(msk) - 1;
        int idx = __shfl_sync(FULLM, biS, src);
        if (lane == 0) { aVS[w] = m; aIS[w] = idx; }
    }
    {
        unsigned vb = __float_as_uint(fmaxf(bvE, 0.0f));
        unsigned m  = __reduce_max_sync(FULLM, vb);
        unsigned msk = __ballot_sync(FULLM, vb == m);
        int src = __ffs(msk) - 1;
        int idx = __shfl_sync(FULLM, biE, src);
        if (lane == 0) { aVE[w] = m; aIE[w] = idx; }
    }
    __syncthreads();

    // Warp 0 finishes start, warp 1 finishes end (8-entry reduce).
    if (w < 2) {
        unsigned vb = 0u;
        int idx = 0;
        if (lane < NW) {
            vb  = (w == 0) ? aVS[lane] : aVE[lane];
            idx = (w == 0) ? aIS[lane] : aIE[lane];
        }
        unsigned m   = __reduce_max_sync(FULLM, vb);
        unsigned msk = __ballot_sync(FULLM, vb == m && lane < NW);
        int src = __ffs(msk) - 1;
        int ans = __shfl_sync(FULLM, idx, src);
        if (lane == 0) out[(w == 0 ? 0 : B) + b] = (float)ans;
    }
}

extern "C" void kernel_launch(void* const* d_in, const int* in_sizes, int n_in,
                              void* d_out, int out_size) {
    const float* start_p = (const float*)d_in[0];
    const float* end_p   = (const float*)d_in[1];
    float* out = (float*)d_out;

    const int B = in_sizes[0] / S_LEN;  // 16
    probs_to_span_kernel<<<B, NT>>>(start_p, end_p, out, B);
}

// round 10
// speedup vs baseline: 1.0048x; 1.0048x over previous
#include <cuda_runtime.h>

// ProbsToSpan: per batch b,
//   predicted_start[b] = argmax_s ( start[b,s] * suffix_max(end[b,:])[s] )
//   predicted_end[b]   = argmax_t ( end[b,t]   * prefix_max(start[b,:])[t] )
// Exact vs. reference (nonneg probs => monotone fp32 multiply; tie -> first idx).
//
// S=4096, B=16. One CTA/batch, 512 threads (16 warps), 8 elems/thread.
// Warp-shuffle scans; argmax via REDUX + ballot. 2 __syncthreads total.
// Kernel wallclock is at the T_ovh/launch floor (~4.9us); structure chosen
// for the shortest measured critical path (R7) with R9's register trims.

#define S_LEN 4096
#define NT    512
#define NW    16    // warps
#define CHK   8     // elements per thread

#define NEGBIG (-1e30f)
#define FULLM  0xFFFFFFFFu

__global__ __launch_bounds__(NT)
void probs_to_span_kernel(const float* __restrict__ start_p,
                          const float* __restrict__ end_p,
                          float* __restrict__ out, int B) {
    __shared__ float wS[NW];               // per-warp total max(start)
    __shared__ float wE[NW];               // per-warp total max(end)
    __shared__ unsigned aVS[NW], aVE[NW];  // per-warp best value bits
    __shared__ int      aIS[NW], aIE[NW];  // per-warp best index

    const int b    = blockIdx.x;
    const int t    = threadIdx.x;
    const int w    = t >> 5;
    const int lane = t & 31;

    const float4* sp = (const float4*)(start_p + (size_t)b * S_LEN);
    const float4* ep = (const float4*)(end_p   + (size_t)b * S_LEN);

    float4 s0 = sp[2 * t], s1 = sp[2 * t + 1];
    float4 e0 = ep[2 * t], e1 = ep[2 * t + 1];

    float s[CHK] = {s0.x, s0.y, s0.z, s0.w, s1.x, s1.y, s1.z, s1.w};
    float e[CHK] = {e0.x, e0.y, e0.z, e0.w, e1.x, e1.y, e1.z, e1.w};

    // Chunk maxes with 4-way ILP (2 levels + combine).
    float smax = fmaxf(fmaxf(fmaxf(s[0], s[4]), fmaxf(s[1], s[5])),
                       fmaxf(fmaxf(s[2], s[6]), fmaxf(s[3], s[7])));
    float emax = fmaxf(fmaxf(fmaxf(e[0], e[4]), fmaxf(e[1], e[5])),
                       fmaxf(fmaxf(e[2], e[6]), fmaxf(e[3], e[7])));

    // Warp-level inclusive prefix max of smax (by lane) and suffix max of emax.
    float ps = smax, se = emax;
#pragma unroll
    for (int off = 1; off < 32; off <<= 1) {
        float vU = __shfl_up_sync(FULLM, ps, off);
        float vD = __shfl_down_sync(FULLM, se, off);
        if (lane >= off)      ps = fmaxf(ps, vU);
        if (lane + off < 32)  se = fmaxf(se, vD);
    }

    // Publish warp totals.
    if (lane == 31) wS[w] = ps;   // inclusive prefix at lane31 == warp total
    if (lane == 0)  wE[w] = se;   // inclusive suffix at lane0  == warp total
    __syncthreads();

    // Cross-warp exclusive head(start) / tail(end) (uniform per warp, broadcast LDS).
    float headS = NEGBIG, tailE = NEGBIG;
#pragma unroll
    for (int i = 0; i < NW; i++) {
        if (i < w) headS = fmaxf(headS, wS[i]);
        if (i > w) tailE = fmaxf(tailE, wE[i]);
    }

    // Exclusive within-warp versions.
    float exS = __shfl_up_sync(FULLM, ps, 1);
    float exE = __shfl_down_sync(FULLM, se, 1);
    if (lane == 0)  exS = NEGBIG;
    if (lane == 31) exE = NEGBIG;

    const float preS = fmaxf(headS, exS);   // max(start) strictly before this chunk
    const float sufE = fmaxf(tailE, exE);   // max(end)   strictly after  this chunk

    // Best start: reverse loop computes suffix-max(end) on the fly.
    // Descending j with >= keeps the SMALLEST index on ties.
    float bvS = -1.0f; int biS = 0;
    float runE = sufE;
#pragma unroll
    for (int j = CHK - 1; j >= 0; j--) {
        runE = fmaxf(runE, e[j]);
        float f = s[j] * runE;
        if (f >= bvS) { bvS = f; biS = t * CHK + j; }
    }

    // Best end: forward loop with prefix-max(start); strict > keeps first index.
    float bvE = -1.0f; int biE = 0;
    float runS = preS;
#pragma unroll
    for (int j = 0; j < CHK; j++) {
        runS = fmaxf(runS, s[j]);
        float g = e[j] * runS;
        if (g > bvE) { bvE = g; biE = t * CHK + j; }
    }

    // Warp argmax via REDUX on fp32 bits (nonneg => order-monotone), then
    // ballot: lowest matching lane holds the smallest index.
    {
        unsigned vb = __float_as_uint(fmaxf(bvS, 0.0f));
        unsigned m  = __reduce_max_sync(FULLM, vb);
        unsigned msk = __ballot_sync(FULLM, vb == m);
        int src = __ffs(msk) - 1;
        int idx = __shfl_sync(FULLM, biS, src);
        if (lane == 0) { aVS[w] = m; aIS[w] = idx; }
    }
    {
        unsigned vb = __float_as_uint(fmaxf(bvE, 0.0f));
        unsigned m  = __reduce_max_sync(FULLM, vb);
        unsigned msk = __ballot_sync(FULLM, vb == m);
        int src = __ffs(msk) - 1;
        int idx = __shfl_sync(FULLM, biE, src);
        if (lane == 0) { aVE[w] = m; aIE[w] = idx; }
    }
    __syncthreads();

    // Warp 0 finishes start, warp 1 finishes end (16-entry reduce).
    if (w < 2) {
        unsigned vb = 0u;
        int idx = 0;
        if (lane < NW) {
            vb  = (w == 0) ? aVS[lane] : aVE[lane];
            idx = (w == 0) ? aIS[lane] : aIE[lane];
        }
        unsigned m   = __reduce_max_sync(FULLM, vb);
        unsigned msk = __ballot_sync(FULLM, vb == m && lane < NW);
        int src = __ffs(msk) - 1;
        int ans = __shfl_sync(FULLM, idx, src);
        if (lane == 0) out[(w == 0 ? 0 : B) + b] = (float)ans;
    }
}

extern "C" void kernel_launch(void* const* d_in, const int* in_sizes, int n_in,
                              void* d_out, int out_size) {
    const float* start_p = (const float*)d_in[0];
    const float* end_p   = (const float*)d_in[1];
    float* out = (float*)d_out;

    const int B = in_sizes[0] / S_LEN;  // 16
    probs_to_span_kernel<<<B, NT>>>(start_p, end_p, out, B);
}